// round 2
// baseline (speedup 1.0000x reference)
#include <cuda_runtime.h>
#include <math_constants.h>

// ---------------- radix-select state (allocation-free: __device__ globals) ---
#define LOWB  20
#define NB1   4096            // top 12 bits
#define NB2   (1u << LOWB)    // low 20 bits: 1,048,576 bins
#define CHUNK 1024
#define NCHUNK (NB2 / CHUNK)  // 1024

__device__ unsigned int g_hist1[NB1];
__device__ unsigned int g_hist2[NB2];
__device__ unsigned int g_part[NCHUNK];
__device__ unsigned int g_b1, g_k2, g_chunk, g_k3;
__device__ float        g_median;

// monotonic key: order-preserving float -> uint
__device__ __forceinline__ unsigned int fkey(float f) {
    unsigned int b = __float_as_uint(f);
    unsigned int mask = (unsigned int)((int)b >> 31) | 0x80000000u;
    return b ^ mask;
}

__global__ void zero_kernel() {
    unsigned int i = blockIdx.x * blockDim.x + threadIdx.x;
    unsigned int stride = gridDim.x * blockDim.x;
    for (unsigned int j = i; j < NB2; j += stride) g_hist2[j] = 0;
    if (i < NB1) g_hist1[i] = 0;
}

// pass 1: histogram of top 12 bits, smem-privatized
__global__ void hist1_kernel(const float4* __restrict__ x, int n4) {
    __shared__ unsigned int sh[NB1];
    for (int i = threadIdx.x; i < NB1; i += blockDim.x) sh[i] = 0;
    __syncthreads();
    int stride = gridDim.x * blockDim.x;
    for (int i = blockIdx.x * blockDim.x + threadIdx.x; i < n4; i += stride) {
        float4 v = x[i];
        atomicAdd(&sh[fkey(v.x) >> LOWB], 1u);
        atomicAdd(&sh[fkey(v.y) >> LOWB], 1u);
        atomicAdd(&sh[fkey(v.z) >> LOWB], 1u);
        atomicAdd(&sh[fkey(v.w) >> LOWB], 1u);
    }
    __syncthreads();
    for (int i = threadIdx.x; i < NB1; i += blockDim.x)
        if (sh[i]) atomicAdd(&g_hist1[i], sh[i]);
}

// select the top-12-bit bin containing rank k (1 block, 1024 thr, 4 bins/thr)
__global__ void select1_kernel(unsigned int k) {
    __shared__ unsigned int ps[1024];
    int t = threadIdx.x;
    unsigned int c0 = g_hist1[t * 4 + 0], c1 = g_hist1[t * 4 + 1];
    unsigned int c2 = g_hist1[t * 4 + 2], c3 = g_hist1[t * 4 + 3];
    unsigned int s = c0 + c1 + c2 + c3;
    ps[t] = s;
    __syncthreads();
    for (int off = 1; off < 1024; off <<= 1) {
        unsigned int v = (t >= off) ? ps[t - off] : 0u;
        __syncthreads();
        ps[t] += v;
        __syncthreads();
    }
    unsigned int incl = ps[t], excl = incl - s;
    if (k >= excl && k < incl) {
        unsigned int r = k - excl, bin;
        if (r < c0)                { bin = t * 4 + 0; }
        else if (r < c0 + c1)      { bin = t * 4 + 1; r -= c0; }
        else if (r < c0 + c1 + c2) { bin = t * 4 + 2; r -= c0 + c1; }
        else                       { bin = t * 4 + 3; r -= c0 + c1 + c2; }
        g_b1 = bin;
        g_k2 = r;
    }
}

// pass 2: histogram of low 20 bits, restricted to the selected top-12 bin
__global__ void hist2_kernel(const float4* __restrict__ x, int n4) {
    unsigned int b1 = g_b1;
    int stride = gridDim.x * blockDim.x;
    for (int i = blockIdx.x * blockDim.x + threadIdx.x; i < n4; i += stride) {
        float4 v = x[i];
        unsigned int u0 = fkey(v.x), u1 = fkey(v.y), u2 = fkey(v.z), u3 = fkey(v.w);
        if ((u0 >> LOWB) == b1) atomicAdd(&g_hist2[u0 & (NB2 - 1u)], 1u);
        if ((u1 >> LOWB) == b1) atomicAdd(&g_hist2[u1 & (NB2 - 1u)], 1u);
        if ((u2 >> LOWB) == b1) atomicAdd(&g_hist2[u2 & (NB2 - 1u)], 1u);
        if ((u3 >> LOWB) == b1) atomicAdd(&g_hist2[u3 & (NB2 - 1u)], 1u);
    }
}

// partial sums over 1024-bin chunks of hist2
__global__ void part2_kernel() {
    __shared__ unsigned int red[256];
    int b = blockIdx.x;
    unsigned int s = 0;
    for (int i = threadIdx.x; i < CHUNK; i += 256) s += g_hist2[b * CHUNK + i];
    red[threadIdx.x] = s;
    __syncthreads();
    for (int off = 128; off > 0; off >>= 1) {
        if (threadIdx.x < off) red[threadIdx.x] += red[threadIdx.x + off];
        __syncthreads();
    }
    if (threadIdx.x == 0) g_part[b] = red[0];
}

// find which chunk contains rank g_k2
__global__ void selchunk_kernel() {
    __shared__ unsigned int ps[1024];
    int t = threadIdx.x;
    unsigned int s = g_part[t];
    unsigned int k = g_k2;
    ps[t] = s;
    __syncthreads();
    for (int off = 1; off < 1024; off <<= 1) {
        unsigned int v = (t >= off) ? ps[t - off] : 0u;
        __syncthreads();
        ps[t] += v;
        __syncthreads();
    }
    unsigned int incl = ps[t], excl = incl - s;
    if (k >= excl && k < incl) { g_chunk = (unsigned int)t; g_k3 = k - excl; }
}

// find the exact bin within the chunk; reconstruct median float bit-exactly
__global__ void selfinal_kernel() {
    __shared__ unsigned int ps[1024];
    int t = threadIdx.x;
    unsigned int chunk = g_chunk;
    unsigned int s = g_hist2[chunk * CHUNK + t];
    unsigned int k = g_k3;
    ps[t] = s;
    __syncthreads();
    for (int off = 1; off < 1024; off <<= 1) {
        unsigned int v = (t >= off) ? ps[t - off] : 0u;
        __syncthreads();
        ps[t] += v;
        __syncthreads();
    }
    unsigned int incl = ps[t], excl = incl - s;
    if (k >= excl && k < incl) {
        unsigned int key  = (g_b1 << LOWB) | (chunk * CHUNK + (unsigned int)t);
        unsigned int bits = (key & 0x80000000u) ? (key ^ 0x80000000u) : ~key;
        g_median = __uint_as_float(bits);
    }
}

// ---------------- fused threshold + 7x7 maxpool + local-max select -----------
#define TW 128
#define TH 32
#define HALO 3
#define SW (TW + 2 * HALO)   // 134
#define SH (TH + 2 * HALO)   // 38
#define IMG_W 2048
#define IMG_H 2048

__global__ __launch_bounds__(256) void nms_kernel(const float* __restrict__ x,
                                                  float* __restrict__ out) {
    __shared__ float sthr[SH][SW];
    __shared__ float shm[SH][TW];
    const float med = g_median;

    int tx = threadIdx.x & 31;
    int ty = threadIdx.x >> 5;          // 32x8 thread layout
    int x0 = blockIdx.x * TW - HALO;
    int y0 = blockIdx.y * TH - HALO;
    const float* img = x + (size_t)blockIdx.z * IMG_W * IMG_H;
    float* oimg = out + (size_t)blockIdx.z * IMG_W * IMG_H;

    // load + threshold; pad with -inf (reference pads maxpool with -inf)
    #pragma unroll
    for (int i = 0; i < 5; i++) {
        int r = ty + 8 * i;
        if (r < SH) {
            int gy = y0 + r;
            bool rowok = (gy >= 0 && gy < IMG_H);
            #pragma unroll
            for (int j = 0; j < 5; j++) {
                int c = tx + 32 * j;
                if (c < SW) {
                    int gx = x0 + c;
                    float v = -CUDART_INF_F;
                    if (rowok && gx >= 0 && gx < IMG_W) {
                        float t = img[(size_t)gy * IMG_W + gx];
                        v = (t > med) ? t : 0.0f;
                    }
                    sthr[r][c] = v;
                }
            }
        }
    }
    __syncthreads();

    // horizontal 7-max
    #pragma unroll
    for (int i = 0; i < 5; i++) {
        int r = ty + 8 * i;
        if (r < SH) {
            #pragma unroll
            for (int j = 0; j < 4; j++) {
                int c = tx + 32 * j;
                float m = sthr[r][c];
                #pragma unroll
                for (int o = 1; o < 7; o++) m = fmaxf(m, sthr[r][c + o]);
                shm[r][c] = m;
            }
        }
    }
    __syncthreads();

    // vertical 7-max + compare + store
    #pragma unroll
    for (int i = 0; i < 4; i++) {
        int r = ty + 8 * i;
        int gy = blockIdx.y * TH + r;
        #pragma unroll
        for (int j = 0; j < 4; j++) {
            int c = tx + 32 * j;
            float m = shm[r][c];
            #pragma unroll
            for (int o = 1; o < 7; o++) m = fmaxf(m, shm[r + o][c]);
            float v = sthr[r + HALO][c + HALO];
            int gx = blockIdx.x * TW + c;
            oimg[(size_t)gy * IMG_W + gx] = (v == m) ? v : 0.0f;
        }
    }
}

// ---------------- launch ----------------------------------------------------
extern "C" void kernel_launch(void* const* d_in, const int* in_sizes, int n_in,
                              void* d_out, int out_size) {
    const float* x = (const float*)d_in[0];
    float* out = (float*)d_out;
    int n = in_sizes[0];                      // 8*1*2048*2048 = 33,554,432
    int n4 = n >> 2;
    unsigned int k = (unsigned int)((n - 1) / 2);   // lower median rank

    zero_kernel<<<2048, 512>>>();
    hist1_kernel<<<2048, 256>>>((const float4*)x, n4);
    select1_kernel<<<1, 1024>>>(k);
    hist2_kernel<<<2048, 256>>>((const float4*)x, n4);
    part2_kernel<<<NCHUNK, 256>>>();
    selchunk_kernel<<<1, 1024>>>();
    selfinal_kernel<<<1, 1024>>>();
    nms_kernel<<<dim3(IMG_W / TW, IMG_H / TH, 8), 256>>>(x, out);
}